// round 5
// baseline (speedup 1.0000x reference)
#include <cuda_runtime.h>

typedef unsigned long long u64;

// ---------------------------------------------------------------------------
//   x:        [32, 64, 128, 128] f32
//   attention:[32, 4]            f32
//   weight:   [4, 64, 64, 3, 3]  f32   (k, oc, ic, ky, kx)
//   bias_p:   [4, 64]            f32
//   out:      [32, 64, 128, 128] f32
// out[b,o,y,x] = sum_{i,ky,kx} w_mix[b,o,i,ky,kx] * x[b,i,y+ky-1,x+kx-1] + b_mix[b,o]
// ---------------------------------------------------------------------------

#define NB   32
#define NC   64
#define HW   128
#define NK   4
#define KK   9
#define WSZ  (NC*NC*KK)

__device__ __align__(16) float g_wmix[NB * WSZ];   // [b][ic*9+kk][oc]
__device__ __align__(16) float g_bmix[NB * NC];

// ---------------- f32x2 helpers --------------------------------------------
__device__ __forceinline__ void fma2(u64 &d, u64 a, u64 b) {
    asm("fma.rn.f32x2 %0, %1, %2, %0;" : "+l"(d) : "l"(a), "l"(b));
}
__device__ __forceinline__ float2 unpack2(u64 v) {
    float2 f;
    asm("mov.b64 {%0, %1}, %2;" : "=f"(f.x), "=f"(f.y) : "l"(v));
    return f;
}

// ---------------------------------------------------------------------------
// Kernel 1: mix weight bank per sample -> [b][ic][kk][oc] (oc fastest).
// ---------------------------------------------------------------------------
__global__ void mix_kernel(const float* __restrict__ att,
                           const float* __restrict__ w,
                           const float* __restrict__ bias_p) {
    const int b = blockIdx.x;
    const float a0 = att[b * NK + 0];
    const float a1 = att[b * NK + 1];
    const float a2 = att[b * NK + 2];
    const float a3 = att[b * NK + 3];

    for (int i2 = threadIdx.x; i2 < WSZ; i2 += blockDim.x) {
        const int kk = i2 % KK;
        const int ic = (i2 / KK) & (NC - 1);
        const int oc = i2 / (KK * NC);
        const float s = a0 * w[i2]
                      + a1 * w[i2 + WSZ]
                      + a2 * w[i2 + 2 * WSZ]
                      + a3 * w[i2 + 3 * WSZ];
        g_wmix[b * WSZ + (ic * KK + kk) * NC + oc] = s;
    }
    if (threadIdx.x < NC) {
        const int oc = threadIdx.x;
        g_bmix[b * NC + oc] = a0 * bias_p[oc]
                            + a1 * bias_p[NC + oc]
                            + a2 * bias_p[2 * NC + oc]
                            + a3 * bias_p[3 * NC + oc];
    }
}

// ---------------------------------------------------------------------------
// Kernel 2: direct conv, f32x2 over oc pairs, input tile staged DUPLICATED
// so the broadcast operand is a single LDS.64 (no alu packing).
//   Block: (sample, 8-oc group, 32x32 tile). 256 thr = 32(x) x 8(row-grp).
//   Thread: 4 rows x 1 col x 8 oc -> 16 f32x2 accumulators.
// ---------------------------------------------------------------------------
#define OCT    8
#define TILE   32
#define ICC    4
#define SIN_W  35   // float2 row stride (34 valid cols + 1 pad)

#define SW_FLOATS   (NC * KK * OCT)                 // 4608
#define SIN_FLOAT2  (ICC * 34 * SIN_W)              // 4760
#define SMEM_BYTES  (SW_FLOATS * 4 + SIN_FLOAT2 * 8) // 56512

__global__ __launch_bounds__(256)
void conv_kernel(const float* __restrict__ x, float* __restrict__ out) {
    extern __shared__ __align__(16) float smem[];
    float*  sW  = smem;                         // [ic*9+kk][oc8]
    float2* sIn = (float2*)(smem + SW_FLOATS);  // [ic][row(34)][col stride 35], (v,v)

    const int tid = threadIdx.x;
    const int tx  = tid & 31;
    const int ty  = tid >> 5;
    const int b   = blockIdx.z;
    const int ocg = blockIdx.y;
    const int tile = blockIdx.x;
    const int ty0 = (tile >> 2) * TILE;
    const int tx0 = (tile & 3) * TILE;

    // Stage this block's mixed-weight slice: sW[(ic*9+kk)*8 + oc]
    {
        const float* wsrc = g_wmix + b * WSZ + ocg * OCT;
        for (int i = tid; i < SW_FLOATS; i += 256) {
            const int oc   = i & (OCT - 1);
            const int ickk = i >> 3;
            sW[i] = wsrc[ickk * NC + oc];
        }
    }

    u64 acc[4][4];
    #pragma unroll
    for (int p = 0; p < 4; p++)
        #pragma unroll
        for (int j = 0; j < 4; j++) acc[p][j] = 0ull;

    const float* xb = x + (size_t)b * NC * HW * HW;

    for (int icb = 0; icb < NC / ICC; icb++) {
        // ---- stage input chunk duplicated: sIn[..] = (v, v)
        for (int i = tid; i < ICC * 34 * 34; i += 256) {
            const int col = i % 34;
            const int row = (i / 34) % 34;
            const int ic  = i / (34 * 34);
            const int gy  = ty0 + row - 1;
            const int gx  = tx0 + col - 1;
            float v = 0.0f;
            if (gy >= 0 && gy < HW && gx >= 0 && gx < HW)
                v = xb[((icb * ICC + ic) * HW + gy) * HW + gx];
            sIn[(ic * 34 + row) * SIN_W + col] = make_float2(v, v);
        }
        __syncthreads();

        // ---- compute (all smem offsets compile-time immediates)
        #pragma unroll
        for (int ic = 0; ic < ICC; ic++) {
            const u64* wrow = (const u64*)&sW[(icb * ICC + ic) * KK * OCT];
            const u64* arow = (const u64*)&sIn[(ic * 34 + 4 * ty) * SIN_W + tx];
            #pragma unroll
            for (int ky = 0; ky < 3; ky++) {
                #pragma unroll
                for (int kx = 0; kx < 3; kx++) {
                    const u64 w0 = wrow[(ky * 3 + kx) * 4 + 0]; // broadcast (free)
                    const u64 w1 = wrow[(ky * 3 + kx) * 4 + 1];
                    const u64 w2 = wrow[(ky * 3 + kx) * 4 + 2];
                    const u64 w3 = wrow[(ky * 3 + kx) * 4 + 3];
                    #pragma unroll
                    for (int pr = 0; pr < 4; pr++) {
                        const u64 a = arow[(pr + ky) * SIN_W + kx]; // (v,v) pair
                        fma2(acc[pr][0], a, w0);
                        fma2(acc[pr][1], a, w1);
                        fma2(acc[pr][2], a, w2);
                        fma2(acc[pr][3], a, w3);
                    }
                }
            }
        }
        __syncthreads();
    }

    // ---- epilogue: bias + store
    const u64* bm = (const u64*)(g_bmix + b * NC + ocg * OCT);
    float* ob = out + (size_t)b * NC * HW * HW + (size_t)(ocg * OCT) * HW * HW;
    #pragma unroll
    for (int j = 0; j < 4; j++) {
        const float2 bias = unpack2(bm[j]);
        #pragma unroll
        for (int pr = 0; pr < 4; pr++) {
            const float2 v = unpack2(acc[pr][j]);
            const int y  = ty0 + 4 * ty + pr;
            const int xo = tx0 + tx;
            ob[(size_t)(2 * j)     * HW * HW + y * HW + xo] = v.x + bias.x;
            ob[(size_t)(2 * j + 1) * HW * HW + y * HW + xo] = v.y + bias.y;
        }
    }
}

// ---------------------------------------------------------------------------
extern "C" void kernel_launch(void* const* d_in, const int* in_sizes, int n_in,
                              void* d_out, int out_size) {
    (void)in_sizes; (void)n_in; (void)out_size;
    const float* x      = (const float*)d_in[0];
    const float* att    = (const float*)d_in[1];
    const float* weight = (const float*)d_in[2];
    const float* bias_p = (const float*)d_in[3];
    float* out = (float*)d_out;

    static int smem_set = 0;
    if (!smem_set) {
        cudaFuncSetAttribute(conv_kernel,
                             cudaFuncAttributeMaxDynamicSharedMemorySize,
                             SMEM_BYTES);
        smem_set = 1;
    }

    mix_kernel<<<NB, 256>>>(att, weight, bias_p);

    dim3 grid(16, NC / OCT, NB);
    conv_kernel<<<grid, 256, SMEM_BYTES>>>(x, out);
}